// round 14
// baseline (speedup 1.0000x reference)
#include <cuda_runtime.h>
#include <cuda_fp16.h>
#include <cstdint>

#define NB  8
#define SLD 1024
#define SLM 1024
#define DD  1024
#define HH  16
#define HS  64

// Scratch: ctx (fp16), X (fp16), Wc (fp16), mem (fp16)
__device__ __half g_ctxh[(size_t)NB * SLD * DD];      // 16 MB
__device__ __half g_xh[(size_t)NB * SLD * DD];        // 16 MB
__device__ __half g_wh[(size_t)DD * 2 * DD];          // 4 MB
__device__ __half g_memh[(size_t)NB * SLM * DD];      // 16 MB

#define QSCALE 0.1803368801111204f   // 0.125 * log2(e)
#define L2E    1.4426950408889634f

__device__ __forceinline__ void mma_f16(float c[4], const unsigned a[4], const unsigned b[2]) {
    asm volatile(
        "mma.sync.aligned.m16n8k16.row.col.f32.f16.f16.f32 "
        "{%0,%1,%2,%3}, {%4,%5,%6,%7}, {%8,%9}, {%0,%1,%2,%3};\n"
        : "+f"(c[0]), "+f"(c[1]), "+f"(c[2]), "+f"(c[3])
        : "r"(a[0]), "r"(a[1]), "r"(a[2]), "r"(a[3]), "r"(b[0]), "r"(b[1]));
}

__device__ __forceinline__ void ldsm4(unsigned r[4], unsigned addr) {
    asm volatile("ldmatrix.sync.aligned.m8n8.x4.shared.b16 {%0,%1,%2,%3}, [%4];"
        : "=r"(r[0]), "=r"(r[1]), "=r"(r[2]), "=r"(r[3]) : "r"(addr));
}

__device__ __forceinline__ void ldsm4t(unsigned r[4], unsigned addr) {
    asm volatile("ldmatrix.sync.aligned.m8n8.x4.trans.shared.b16 {%0,%1,%2,%3}, [%4];"
        : "=r"(r[0]), "=r"(r[1]), "=r"(r[2]), "=r"(r[3]) : "r"(addr));
}

__device__ __forceinline__ void cp16(unsigned saddr, const void* gptr) {
    asm volatile("cp.async.cg.shared.global [%0], [%1], 16;\n" :: "r"(saddr), "l"(gptr));
}

__device__ __forceinline__ unsigned packh2(float x, float y) {
    __half2 h = __floats2half2_rn(x, y);
    return *(unsigned*)&h;
}

__device__ __forceinline__ unsigned ex2h2(unsigned x) {
    unsigned y;
    asm("ex2.approx.f16x2 %0, %1;" : "=r"(y) : "r"(x));
    return y;
}

// ==================== prep: RN-round fp32 -> fp16 in memory ====================
__global__ __launch_bounds__(256)
void round_half_kernel(const float* __restrict__ src, __half* __restrict__ dst, int n4)
{
    int i = blockIdx.x * 256 + threadIdx.x;
    if (i < n4) {
        float4 v = ((const float4*)src)[i];
        __half2 h0 = __floats2half2_rn(v.x, v.y);
        __half2 h1 = __floats2half2_rn(v.z, v.w);
        uint2 o;
        o.x = *(unsigned*)&h0;
        o.y = *(unsigned*)&h1;
        *(uint2*)&dst[(size_t)i * 4] = o;
    }
}

// ==================== flash attention: fp16 mma + ldmatrix + f16x2 ex2 ====================
#define BQ 128
#define BK 64
#define AT 128
#define LDHB 144                      // smem row stride bytes (72 halves)

#define OFF_Q   0                     // 128*144 = 18432 B
#define OFF_K0  18432                 // 64*144 = 9216 B
#define OFF_K1  27648                 // 9216 B
#define OFF_MB  36864                 // mask fp32, 4096 B
#define ATT_SMEM_BYTES (OFF_MB + 4096)   // 40960 B

__global__ __launch_bounds__(AT, 2)
void attn_kernel(const float* __restrict__ inp,
                 const float* __restrict__ maskp)
{
    extern __shared__ __align__(16) char smb[];
    const unsigned sbase = (unsigned)__cvta_generic_to_shared(smb);
    float* smf = (float*)(smb + OFF_MB);

    const int tid  = threadIdx.x;
    const int lane = tid & 31;
    const int warp = tid >> 5;     // 0..3
    const int g = lane >> 2;       // 0..7
    const int q = lane & 3;        // 0..3
    const int quad = lane >> 3;    // 0..3
    const int rl = lane & 7;       // 0..7
    const int qt = blockIdx.x, h = blockIdx.y, b = blockIdx.z;
    const int qrow = warp * 32;    // warp's first query row in tile

    const __half* kbase = g_memh + (size_t)b * SLM * DD + h * HS;

    auto cpK = [&](int kt, int buf) {
        const unsigned base = sbase + (buf ? OFF_K1 : OFF_K0);
        #pragma unroll
        for (int t = 0; t < 4; t++) {
            int idx = tid + t * AT;            // 0..511
            int r = idx >> 3, c = idx & 7;     // key row 0..63, 16B chunk 0..7
            cp16(base + (unsigned)(r * LDHB + c * 16),
                 kbase + (size_t)(kt * BK + r) * DD + c * 8);
        }
        asm volatile("cp.async.commit_group;\n" ::: "memory");
    };
    cpK(0, 0);

    // stage Q tile [128][64] fp32*QSCALE -> fp16; mask pre-scaled by log2(e)
    const float* qbase = inp + ((size_t)(b * SLD + qt * BQ)) * DD + h * HS;
    #pragma unroll
    for (int t = 0; t < 16; t++) {
        int idx = tid + t * AT;                // 0..2047 float4s
        int r = idx >> 4, c4 = idx & 15;
        float4 v = *(const float4*)(qbase + (size_t)r * DD + c4 * 4);
        uint2 o;
        o.x = packh2(v.x * QSCALE, v.y * QSCALE);
        o.y = packh2(v.z * QSCALE, v.w * QSCALE);
        *(uint2*)(smb + OFF_Q + r * LDHB + c4 * 8) = o;
    }
    for (int i = tid; i < SLM; i += AT)
        smf[i] = (-1e30f * L2E) * (1.0f - maskp[(size_t)b * SLM + i]);

    float oc[2][8][4] = {};
    float lacc[2][4] = {};               // l via ones-column mma (col 0)
    int buf = 0;
    const unsigned bones = (g == 0) ? 0x3C003C00u : 0u;   // B[k][0]=1, others 0
    const unsigned bones_frag[2] = {bones, bones};

    for (int kt = 0; kt < SLM / BK; kt++) {
        asm volatile("cp.async.wait_group 0;\n" ::: "memory");
        __syncthreads();
        if (kt + 1 < SLM / BK) cpK(kt + 1, buf ^ 1);

        const unsigned sK = sbase + (buf ? OFF_K1 : OFF_K0);

        // ---- S' = (Q*qscale) K^T : 32 rows x 64 keys ----
        float sc[2][8][4] = {};
        #pragma unroll
        for (int kk = 0; kk < 4; kk++) {
            unsigned a[2][4];
            #pragma unroll
            for (int mf = 0; mf < 2; mf++) {
                int row = qrow + mf * 16 + (quad & 1) * 8 + rl;
                int colh = kk * 16 + (quad >> 1) * 8;
                ldsm4(a[mf], sbase + OFF_Q + (unsigned)(row * LDHB + colh * 2));
            }
            unsigned bb[8][2];
            #pragma unroll
            for (int j2 = 0; j2 < 8; j2 += 2) {
                int row = (j2 + (quad >> 1)) * 8 + rl;
                int colh = kk * 16 + (quad & 1) * 8;
                unsigned bt[4];
                ldsm4(bt, sK + (unsigned)(row * LDHB + colh * 2));
                bb[j2][0] = bt[0]; bb[j2][1] = bt[1];
                bb[j2 + 1][0] = bt[2]; bb[j2 + 1][1] = bt[3];
            }
            #pragma unroll
            for (int mf = 0; mf < 2; mf++)
                #pragma unroll
                for (int j = 0; j < 8; j++)
                    mma_f16(sc[mf][j], a[mf], bb[j]);
        }

        // ---- p = ex2.f16x2(s' + m') -> packed A-frag halves directly ----
        unsigned ph[2][8][2];
        #pragma unroll
        for (int j = 0; j < 8; j++) {
            float2 mv = *(const float2*)&smf[kt * 64 + j * 8 + 2 * q];
            #pragma unroll
            for (int mf = 0; mf < 2; mf++) {
                ph[mf][j][0] = ex2h2(packh2(sc[mf][j][0] + mv.x, sc[mf][j][1] + mv.y));
                ph[mf][j][1] = ex2h2(packh2(sc[mf][j][2] + mv.x, sc[mf][j][3] + mv.y));
            }
        }

        // ---- O += P V, l += P @ ones : B via ldmatrix.trans ----
        #pragma unroll
        for (int t = 0; t < 4; t++) {
            unsigned aP[2][4];
            #pragma unroll
            for (int mf = 0; mf < 2; mf++) {
                aP[mf][0] = ph[mf][2 * t][0];
                aP[mf][1] = ph[mf][2 * t][1];
                aP[mf][2] = ph[mf][2 * t + 1][0];
                aP[mf][3] = ph[mf][2 * t + 1][1];
            }
            unsigned bb[8][2];
            #pragma unroll
            for (int nf2 = 0; nf2 < 8; nf2 += 2) {
                int row = 16 * t + (quad & 1) * 8 + rl;
                int colh = (nf2 + (quad >> 1)) * 8;
                unsigned bt[4];
                ldsm4t(bt, sK + (unsigned)(row * LDHB + colh * 2));
                bb[nf2][0] = bt[0]; bb[nf2][1] = bt[1];
                bb[nf2 + 1][0] = bt[2]; bb[nf2 + 1][1] = bt[3];
            }
            #pragma unroll
            for (int mf = 0; mf < 2; mf++) {
                #pragma unroll
                for (int nf = 0; nf < 8; nf++)
                    mma_f16(oc[mf][nf], aP[mf], bb[nf]);
                mma_f16(lacc[mf], aP[mf], bones_frag);
            }
        }
        buf ^= 1;
    }

    // ---- normalize (l from acc col 0, q=0 lanes), round to fp16, write ctx ----
    #pragma unroll
    for (int mf = 0; mf < 2; mf++) {
        float l0 = __shfl_sync(0xffffffffu, lacc[mf][0], lane & ~3);
        float l1 = __shfl_sync(0xffffffffu, lacc[mf][2], lane & ~3);
        const float inv0 = 1.0f / l0;
        const float inv1 = 1.0f / l1;
        __half* obase = g_ctxh + ((size_t)(b * SLD + qt * BQ + qrow + mf * 16)) * DD + h * HS;
        #pragma unroll
        for (int nf = 0; nf < 8; nf++) {
            __half2 v;
            v = __floats2half2_rn(oc[mf][nf][0] * inv0, oc[mf][nf][1] * inv0);
            *(__half2*)&obase[(size_t)g * DD + nf * 8 + 2 * q] = v;
            v = __floats2half2_rn(oc[mf][nf][2] * inv1, oc[mf][nf][3] * inv1);
            *(__half2*)&obase[(size_t)(g + 8) * DD + nf * 8 + 2 * q] = v;
        }
    }
}

// ==================== fused projection GEMM (K=2048, fp16, ldmatrix) ====================
#define TM2 128
#define TN2 128
#define GBK 32
#define GLH 40
#define GT2 128
#define STG_BYTES ((TM2 + TN2) * GLH * 2)        // 20480 B per stage
#define GEMM_SMEM_BYTES (3 * STG_BYTES)          // 61440 B

__device__ __forceinline__ float gated_act(float o) {
    o = fminf(fmaxf(o, -30.0f), 30.0f);
    float e = __expf(-o);
    return (1.0f - e) / (1.0f + e * e);   // == sigmoid(o)*tanh(o)
}

__global__ __launch_bounds__(GT2, 2)
void out_gemm_kernel(const float* __restrict__ bc, float* __restrict__ outp)
{
    extern __shared__ __align__(16) char sgb[];
    const unsigned sbase = (unsigned)__cvta_generic_to_shared(sgb);

    const int tid  = threadIdx.x;
    const int lane = tid & 31;
    const int warp = tid >> 5;      // 0..3
    const int g = lane >> 2;
    const int q = lane & 3;
    const int quad = lane >> 3;    // 0..3
    const int rl = lane & 7;       // 0..7
    const int wm = warp >> 1;       // 0..1 -> rows wm*64
    const int wn = warp & 1;        // 0..1 -> cols wn*64
    const int n0 = blockIdx.x * TN2;
    const int m0 = blockIdx.y * TM2;

    auto stage = [&](int kb, int s) {
        const __half* src = (kb < DD) ? g_xh : g_ctxh;
        const int koff = kb & (DD - 1);
        const unsigned bx = sbase + (unsigned)(s * STG_BYTES);
        const unsigned bw = bx + (unsigned)(TM2 * GLH * 2);
        #pragma unroll
        for (int t = 0; t < 4; t++) {
            int idx = tid + t * GT2;            // 0..511
            int r = idx >> 2, c = idx & 3;      // row 0..127, 16B chunk 0..3
            cp16(bx + (unsigned)(r * GLH * 2 + c * 16),
                 src + (size_t)(m0 + r) * DD + koff + c * 8);
            cp16(bw + (unsigned)(r * GLH * 2 + c * 16),
                 g_wh + (size_t)(n0 + r) * (2 * DD) + kb + c * 8);
        }
        asm volatile("cp.async.commit_group;" ::: "memory");
    };

    stage(0, 0);
    stage(GBK, 1);

    float acc[4][8][4] = {};

    for (int i = 0; i < 2 * DD / GBK; i++) {    // 64 iterations
        if (i + 1 < 2 * DD / GBK)
            asm volatile("cp.async.wait_group 1;" ::: "memory");
        else
            asm volatile("cp.async.wait_group 0;" ::: "memory");
        __syncthreads();
        if (i + 2 < 2 * DD / GBK) stage((i + 2) * GBK, (i + 2) % 3);

        const unsigned sX = sbase + (unsigned)((i % 3) * STG_BYTES);
        const unsigned sW = sX + (unsigned)(TM2 * GLH * 2);

        #pragma unroll
        for (int kk = 0; kk < GBK; kk += 16) {
            unsigned a[4][4], bb[8][2];
            #pragma unroll
            for (int mi = 0; mi < 4; mi++) {
                int row = wm * 64 + mi * 16 + (quad & 1) * 8 + rl;
                int colh = kk + (quad >> 1) * 8;
                ldsm4(a[mi], sX + (unsigned)(row * GLH * 2 + colh * 2));
            }
            #pragma unroll
            for (int ni2 = 0; ni2 < 8; ni2 += 2) {
                int row = wn * 64 + (ni2 + (quad >> 1)) * 8 + rl;
                int colh = kk + (quad & 1) * 8;
                unsigned bt[4];
                ldsm4(bt, sW + (unsigned)(row * GLH * 2 + colh * 2));
                bb[ni2][0] = bt[0]; bb[ni2][1] = bt[1];
                bb[ni2 + 1][0] = bt[2]; bb[ni2 + 1][1] = bt[3];
            }
            #pragma unroll
            for (int mi = 0; mi < 4; mi++)
                #pragma unroll
                for (int ni = 0; ni < 8; ni++)
                    mma_f16(acc[mi][ni], a[mi], bb[ni]);
        }
    }

    // ---- epilogue: bias + sigmoid*tanh, direct to global ----
    #pragma unroll
    for (int ni = 0; ni < 8; ni++) {
        int col = n0 + wn * 64 + ni * 8 + 2 * q;
        float b0 = bc[col], b1 = bc[col + 1];
        #pragma unroll
        for (int mi = 0; mi < 4; mi++) {
            int row = m0 + wm * 64 + mi * 16 + g;
            float2 v0, v1;
            v0.x = gated_act(acc[mi][ni][0] + b0);
            v0.y = gated_act(acc[mi][ni][1] + b1);
            v1.x = gated_act(acc[mi][ni][2] + b0);
            v1.y = gated_act(acc[mi][ni][3] + b1);
            *(float2*)&outp[(size_t)row * DD + col]       = v0;
            *(float2*)&outp[(size_t)(row + 8) * DD + col] = v1;
        }
    }
}

extern "C" void kernel_launch(void* const* d_in, const int* in_sizes, int n_in,
                              void* d_out, int out_size)
{
    const float* inp  = (const float*)d_in[0];   // [8,1024,1024]
    const float* mem  = (const float*)d_in[1];   // [8,1024,1024]
    const float* mask = (const float*)d_in[2];   // [8,1024]
    const float* Wc   = (const float*)d_in[3];   // [1024,2048]
    const float* bc   = (const float*)d_in[4];   // [1024]
    float* outp = (float*)d_out;                 // [8,1024,1024]

    // one-time setup (first call = correctness run, NOT under graph capture)
    static cudaStream_t s2 = nullptr;
    static cudaEvent_t evFork = nullptr, evJoin = nullptr;
    if (!s2) {
        cudaStreamCreate(&s2);
        cudaEventCreateWithFlags(&evFork, cudaEventDisableTiming);
        cudaEventCreateWithFlags(&evJoin, cudaEventDisableTiming);
        cudaFuncSetAttribute(attn_kernel, cudaFuncAttributeMaxDynamicSharedMemorySize,
                             ATT_SMEM_BYTES);
        cudaFuncSetAttribute(out_gemm_kernel, cudaFuncAttributeMaxDynamicSharedMemorySize,
                             GEMM_SMEM_BYTES);
    }

    __half *xh_p, *wh_p, *memh_p;
    cudaGetSymbolAddress((void**)&xh_p, g_xh);
    cudaGetSymbolAddress((void**)&wh_p, g_wh);
    cudaGetSymbolAddress((void**)&memh_p, g_memh);

    // fork: W/X fp16 rounding on s2 (overlaps attention)
    cudaEventRecord(evFork, 0);
    cudaStreamWaitEvent(s2, evFork, 0);
    {
        int n4w = DD * 2 * DD / 4;       // 524288
        round_half_kernel<<<n4w / 256, 256, 0, s2>>>(Wc, wh_p, n4w);
        int n4x = NB * SLD * DD / 4;     // 2097152
        round_half_kernel<<<n4x / 256, 256, 0, s2>>>(inp, xh_p, n4x);
    }
    cudaEventRecord(evJoin, s2);

    // stream 0: mem -> fp16, then attention
    {
        int n4m = NB * SLM * DD / 4;     // 2097152
        round_half_kernel<<<n4m / 256, 256>>>(mem, memh_p, n4m);
    }
    dim3 agrid(SLD / BQ, HH, NB);              // 8 x 16 x 8 = 1024 blocks
    attn_kernel<<<agrid, AT, ATT_SMEM_BYTES>>>(inp, mask);

    // join, then fused projection GEMM + epilogue
    cudaStreamWaitEvent(0, evJoin, 0);
    dim3 ggrid(DD / TN2, (NB * SLD) / TM2);    // 8 x 64 = 512 blocks
    out_gemm_kernel<<<ggrid, GT2, GEMM_SMEM_BYTES>>>(bc, outp);
}